// round 5
// baseline (speedup 1.0000x reference)
#include <cuda_runtime.h>
#include <math.h>

#define H 256
#define W 256
#define V 192
#define D 256
#define S 256
#define HW (H*W)

#define SQRT2_D 1.4142135623730951
#define DPf     ((float)(2.0 * SQRT2_D * 128.0 / 255.0))   /* sample spacing, 128-scaled px */
#define OFFf    ((float)(-SQRT2_D * 128.0))
#define INV_DPf ((float)(255.0 / (256.0 * SQRT2_D)))
#define DTf     ((float)(2.0 * SQRT2_D / 256.0))
#define PI_D    3.141592653589793

__device__ float2  g_img2[HW];      // (imgA, imgB) interleaved, row-major
__device__ float2  g_img2T[HW];     // same, transposed: [x*256 + y]
__device__ float2  g_temp[V * D];   // residual sinogram, (A,B) interleaved
__device__ float4  g_trig4[V];      // {svDP, cvDP, svI, cvI} for bwd
__device__ float2  g_trigB[V];      // raw {cv, sv} for fwd
__device__ ushort4 g_bounds[V * D]; // per-ray {kLo, kiLo, kiHi, kHi}

__device__ __forceinline__ void slab(float A, float dir, float b0, float b1,
                                     float& lo, float& hi, bool& empty) {
    if (fabsf(dir) > 1e-7f) {
        float r = 1.0f / dir;
        float t1 = (b0 - A) * r, t2 = (b1 - A) * r;
        lo = fmaxf(lo, fminf(t1, t2));
        hi = fminf(hi, fmaxf(t1, t2));
    } else if (A < b0 || A > b1) {
        empty = true;
    }
}

// ---------------------------------------------------------------------------
// prep: (a) interleave both images + build transposed copy (16x16 smem tiles,
// all accesses coalesced); (b) trig tables; (c) per-ray k-bounds table.
// Block b handles tile b AND (for b<192) all 256 rays of angle v=b (d=tid).
// ---------------------------------------------------------------------------
__global__ void __launch_bounds__(256) prep_kernel(const float* __restrict__ img) {
    __shared__ float2 tile[16][17];
    const int tid = threadIdx.x;
    const int tx = tid & 15, ty = tid >> 4;
    const int bx = (blockIdx.x & 15) << 4;
    const int by = (blockIdx.x >> 4) << 4;

    // --- image interleave + transpose ---
    {
        int p = (by + ty) * W + bx + tx;
        float2 val = make_float2(img[p], img[p + HW]);
        g_img2[p] = val;
        tile[ty][tx] = val;
    }

    // --- ray setup (angle v = blockIdx.x, detector d = tid) ---
    if (blockIdx.x < V) {
        const int v = blockIdx.x, d = tid;
        float cv, sv;
        float af = (float)((double)v * (PI_D / 192.0));
        sincosf(af, &sv, &cv);
        if (d == 0) {
            g_trigB[v] = make_float2(cv, sv);
            g_trig4[v] = make_float4(sv * DPf, cv * DPf, sv * INV_DPf, cv * INV_DPf);
        }
        const float s128 = fmaf((float)d, DPf, OFFf);
        const float ax0 = fmaf(-s128, sv, 127.5f);
        const float ay0 = fmaf( s128, cv, 127.5f);
        const bool steep = fabsf(sv) > fabsf(cv);
        const float c2 = steep ? sv : cv;
        const float s2 = steep ? cv : sv;
        const float ax = steep ? ay0 : ax0;
        const float ay = steep ? ax0 : ay0;

        float lo = -1e30f, hi = 1e30f, li = -1e30f, hii = 1e30f;
        bool empty = false, iempty = false;
        slab(ax, c2, -1.001f, 256.001f, lo, hi, empty);
        slab(ay, s2, -1.001f, 256.001f, lo, hi, empty);
        slab(ax, c2, 0.001f, 254.999f, li, hii, iempty);
        slab(ay, s2, 0.001f, 254.999f, li, hii, iempty);

        int kLo = 1, kHi = 0, kiLo = 1, kiHi = 0;   // empty sentinel
        if (!empty && lo <= hi) {
            kLo = max(0,     (int)ceilf ((lo - OFFf) * INV_DPf - 0.001f));
            kHi = min(S - 1, (int)floorf((hi - OFFf) * INV_DPf + 0.001f));
            if (kLo > kHi) { kLo = 1; kHi = 0; kiLo = 1; kiHi = 0; }
            else if (iempty || li > hii) { kiLo = kHi + 1; kiHi = kHi; }
            else {
                kiLo = max(kLo, (int)ceilf ((li  - OFFf) * INV_DPf + 0.001f));
                kiHi = min(kHi, (int)floorf((hii - OFFf) * INV_DPf - 0.001f));
                if (kiLo > kiHi) { kiLo = kHi + 1; kiHi = kHi; }
            }
        }
        g_bounds[v * D + d] = make_ushort4((unsigned short)kLo, (unsigned short)kiLo,
                                           (unsigned short)kiHi, (unsigned short)kHi);
    }

    __syncthreads();
    {
        int xo = bx + ty, yo = by + tx;
        g_img2T[xo * H + yo] = tile[tx][ty];
    }
}

__device__ __forceinline__ void accum4(float2 p00, float2 p10, float2 p01, float2 p11,
                                       float fx, float fy, float& sA, float& sB) {
    float gx = 1.f - fx, gy = 1.f - fy;
    float w00 = gx * gy, w10 = fx * gy, w01 = gx * fy, w11 = fx * fy;
    sA = fmaf(p00.x, w00, fmaf(p10.x, w10, fmaf(p01.x, w01, fmaf(p11.x, w11, sA))));
    sB = fmaf(p00.y, w00, fmaf(p10.y, w10, fmaf(p01.y, w01, fmaf(p11.y, w11, sB))));
}

// ---------------------------------------------------------------------------
// forward projection: one warp per (v,d) ray, lanes stride over samples.
// Steep angles read the transposed image (bitwise-identical bilinear).
// Setup (trig, bounds) comes from prep's tables — minimal per-ray overhead.
// ---------------------------------------------------------------------------
__global__ void __launch_bounds__(256) fwd_kernel(const float* __restrict__ proj) {
    const int warp = (blockIdx.x * blockDim.x + threadIdx.x) >> 5;
    const int lane = threadIdx.x & 31;
    const int v = warp >> 8;
    const int d = warp & 255;

    const float2 tv = g_trigB[v];
    const float cv = tv.x, sv = tv.y;
    const ushort4 bn = g_bounds[warp];
    const int kLo = bn.x, kiLo = bn.y, kiHi = bn.z, kHi = bn.w;

    const float s128 = fmaf((float)d, DPf, OFFf);
    const float ax0 = fmaf(-s128, sv, 127.5f);
    const float ay0 = fmaf( s128, cv, 127.5f);
    const bool steep = fabsf(sv) > fabsf(cv);
    const float2* __restrict__ im = steep ? g_img2T : g_img2;
    const float c2 = steep ? sv : cv;
    const float s2 = steep ? cv : sv;
    const float ax = steep ? ay0 : ax0;
    const float ay = steep ? ax0 : ay0;

    float sA = 0.f, sB = 0.f;

    // boundary prologue
    for (int k = kLo + lane; k < kiLo; k += 32) {
        float t128 = fmaf((float)k, DPf, OFFf);
        float xp = fmaf(t128, c2, ax), yp = fmaf(t128, s2, ay);
        float x0f = floorf(xp), y0f = floorf(yp);
        int ix0 = (int)x0f, iy0 = (int)y0f;
        int base = iy0 * W + ix0;
        float2 z = make_float2(0.f, 0.f);
        float2 p00 = z, p10 = z, p01 = z, p11 = z;
        bool vx0 = (unsigned)ix0       < (unsigned)W;
        bool vx1 = (unsigned)(ix0 + 1) < (unsigned)W;
        bool vy0 = (unsigned)iy0       < (unsigned)H;
        bool vy1 = (unsigned)(iy0 + 1) < (unsigned)H;
        if (vx0 && vy0) p00 = im[base];
        if (vx1 && vy0) p10 = im[base + 1];
        if (vx0 && vy1) p01 = im[base + W];
        if (vx1 && vy1) p11 = im[base + W + 1];
        accum4(p00, p10, p01, p11, xp - x0f, yp - y0f, sA, sB);
    }
    // interior: zero checks
    for (int k = kiLo + lane; k <= kiHi; k += 32) {
        float t128 = fmaf((float)k, DPf, OFFf);
        float xp = fmaf(t128, c2, ax), yp = fmaf(t128, s2, ay);
        float x0f = floorf(xp), y0f = floorf(yp);
        int base = (int)y0f * W + (int)x0f;
        float2 p00 = im[base],     p10 = im[base + 1];
        float2 p01 = im[base + W], p11 = im[base + W + 1];
        accum4(p00, p10, p01, p11, xp - x0f, yp - y0f, sA, sB);
    }
    // boundary epilogue
    for (int k = max(kiHi + 1, kLo) + lane; k <= kHi; k += 32) {
        float t128 = fmaf((float)k, DPf, OFFf);
        float xp = fmaf(t128, c2, ax), yp = fmaf(t128, s2, ay);
        float x0f = floorf(xp), y0f = floorf(yp);
        int ix0 = (int)x0f, iy0 = (int)y0f;
        int base = iy0 * W + ix0;
        float2 z = make_float2(0.f, 0.f);
        float2 p00 = z, p10 = z, p01 = z, p11 = z;
        bool vx0 = (unsigned)ix0       < (unsigned)W;
        bool vx1 = (unsigned)(ix0 + 1) < (unsigned)W;
        bool vy0 = (unsigned)iy0       < (unsigned)H;
        bool vy1 = (unsigned)(iy0 + 1) < (unsigned)H;
        if (vx0 && vy0) p00 = im[base];
        if (vx1 && vy0) p10 = im[base + 1];
        if (vx0 && vy1) p01 = im[base + W];
        if (vx1 && vy1) p11 = im[base + W + 1];
        accum4(p00, p10, p01, p11, xp - x0f, yp - y0f, sA, sB);
    }

    #pragma unroll
    for (int o = 16; o; o >>= 1) {
        sA += __shfl_xor_sync(0xffffffffu, sA, o);
        sB += __shfl_xor_sync(0xffffffffu, sB, o);
    }
    if (lane == 0) {
        g_temp[warp] = make_float2(fmaf(DTf, sA, -__ldg(proj + warp)),
                                   fmaf(DTf, sB, -__ldg(proj + V * D + warp)));
    }
}

// ---------------------------------------------------------------------------
// backprojection + update with 180-degree point-symmetry pairing:
// each thread handles pixel p (top half) AND its mirror pm = 65535-p.
// Mirror weights are exactly (q1, q0) at detector indices (254-j0, 255-j0).
// ---------------------------------------------------------------------------
__global__ void __launch_bounds__(128) bwd_kernel(const float* __restrict__ wptr,
                                                  float* __restrict__ out) {
    __shared__ float4 sg[V];
    const int tid = threadIdx.x;
    #pragma unroll
    for (int i = tid; i < V; i += 128) sg[i] = g_trig4[i];
    __syncthreads();

    const int p  = blockIdx.x * 128 + tid;      // 0 .. 32767  (iy in [0,128))
    const int pm = (HW - 1) - p;                // point mirror
    const int ix = p & (W - 1);
    const int iy = p >> 8;
    const float px = (float)ix - 127.5f;
    const float py = (float)iy - 127.5f;
    const float npx = -px;

    float accA = 0.f, accB = 0.f, accAm = 0.f, accBm = 0.f;
    const float2* __restrict__ row = g_temp;

    #pragma unroll 2
    for (int v = 0; v < V; ++v, row += D) {
        const float4 q = sg[v];
        const float svDP = q.x, cvDP = q.y, svI = q.z, cvI = q.w;

        const float jc = fmaf(py, cvI, fmaf(npx, svI, 127.5f));
        const float kc = fmaf(px, cvI, fmaf(py,  svI, 127.5f));
        const float jf = floorf(jc), kf = floorf(kc);
        const float fj = jc - jf,    fk = kc - kf;
        const int   j0 = (int)jf;

        const float fkc = fk * cvDP, fks = fk * svDP;
        const float dx00 = fmaf(fj, svDP, -fkc);
        const float u    = fmaf(fj, cvDP,  fks);
        const float dx10 = dx00 - svDP;
        const float dx01 = dx00 + cvDP;
        const float dx11 = dx10 + cvDP;
        const float e10  = u - cvDP;
        const float e01  = u - svDP;
        const float e11  = e10 - svDP;

        const float hx00 = __saturatef(1.f - fabsf(dx00));
        const float hx10 = __saturatef(1.f - fabsf(dx10));
        const float hx01 = __saturatef(1.f - fabsf(dx01));
        const float hx11 = __saturatef(1.f - fabsf(dx11));
        const float hy00 = __saturatef(1.f - fabsf(u));
        const float hy10 = __saturatef(1.f - fabsf(e10));
        const float hy01 = __saturatef(1.f - fabsf(e01));
        const float hy11 = __saturatef(1.f - fabsf(e11));

        const float q0 = fmaf(hx01, hy01, hx00 * hy00);
        const float q1 = fmaf(hx11, hy11, hx10 * hy10);

        const float2 t0 = __ldg(row + j0);
        const float2 t1 = __ldg(row + j0 + 1);
        const float2 m0 = __ldg(row + (254 - j0));
        const float2 m1 = __ldg(row + (255 - j0));
        accA  = fmaf(t0.x, q0, fmaf(t1.x, q1, accA));
        accB  = fmaf(t0.y, q0, fmaf(t1.y, q1, accB));
        accAm = fmaf(m0.x, q1, fmaf(m1.x, q0, accAm));
        accBm = fmaf(m0.y, q1, fmaf(m1.y, q0, accBm));
    }

    const float wdt = __ldg(wptr) * DTf;
    const float2 ia = g_img2[p];
    const float2 ib = g_img2[pm];
    out[p]       = fmaf(-wdt, accA,  ia.x);
    out[p  + HW] = fmaf(-wdt, accB,  ia.y);
    out[pm]      = fmaf(-wdt, accAm, ib.x);
    out[pm + HW] = fmaf(-wdt, accBm, ib.y);
}

// ---------------------------------------------------------------------------
extern "C" void kernel_launch(void* const* d_in, const int* in_sizes, int n_in,
                              void* d_out, int out_size) {
    const float* img  = (const float*)d_in[0];   // [2,1,256,256]
    const float* proj = (const float*)d_in[1];   // [2,1,192,256]
    const float* wptr = (const float*)d_in[2];   // [1]
    float* out = (float*)d_out;                  // [2,1,256,256]

    prep_kernel<<<256, 256>>>(img);
    fwd_kernel<<<(V * D * 32) / 256, 256>>>(proj);
    bwd_kernel<<<(HW / 2) / 128, 128>>>(wptr, out);
}

// round 6
// speedup vs baseline: 1.3052x; 1.3052x over previous
#include <cuda_runtime.h>
#include <math.h>

#define H 256
#define W 256
#define V 192
#define D 256
#define S 256
#define HW (H*W)

#define SQRT2_D 1.4142135623730951
#define DPf     ((float)(2.0 * SQRT2_D * 128.0 / 255.0))   /* sample spacing, 128-scaled px */
#define OFFf    ((float)(-SQRT2_D * 128.0))
#define INV_DPf ((float)(255.0 / (256.0 * SQRT2_D)))
#define DTf     ((float)(2.0 * SQRT2_D / 256.0))
#define PI_D    3.141592653589793

__device__ float2  g_img2[HW];      // (imgA, imgB) interleaved, row-major
__device__ float2  g_img2T[HW];     // same, transposed: [x*256 + y]
__device__ float2  g_temp[V * D];   // residual sinogram, (A,B) interleaved
__device__ float4  g_trig4[V];      // {svDP, cvDP, svI, cvI} for bwd
__device__ float2  g_trigB[V];      // raw {cv, sv} for fwd
__device__ ushort4 g_bounds[V * D]; // per-ray {kLo, kiLo, kiHi, kHi}

__device__ __forceinline__ void slab(float A, float dir, float b0, float b1,
                                     float& lo, float& hi, bool& empty) {
    if (fabsf(dir) > 1e-7f) {
        float r = 1.0f / dir;
        float t1 = (b0 - A) * r, t2 = (b1 - A) * r;
        lo = fmaxf(lo, fminf(t1, t2));
        hi = fminf(hi, fmaxf(t1, t2));
    } else if (A < b0 || A > b1) {
        empty = true;
    }
}

// ---------------------------------------------------------------------------
// prep: (a) interleave both images + build transposed copy (16x16 smem tiles);
// (b) trig tables; (c) per-ray k-bounds table (block b = angle b for b<192).
// ---------------------------------------------------------------------------
__global__ void __launch_bounds__(256) prep_kernel(const float* __restrict__ img) {
    __shared__ float2 tile[16][17];
    const int tid = threadIdx.x;
    const int tx = tid & 15, ty = tid >> 4;
    const int bx = (blockIdx.x & 15) << 4;
    const int by = (blockIdx.x >> 4) << 4;

    {
        int p = (by + ty) * W + bx + tx;
        float2 val = make_float2(img[p], img[p + HW]);
        g_img2[p] = val;
        tile[ty][tx] = val;
    }

    if (blockIdx.x < V) {
        const int v = blockIdx.x, d = tid;
        float cv, sv;
        float af = (float)((double)v * (PI_D / 192.0));
        sincosf(af, &sv, &cv);
        if (d == 0) {
            g_trigB[v] = make_float2(cv, sv);
            g_trig4[v] = make_float4(sv * DPf, cv * DPf, sv * INV_DPf, cv * INV_DPf);
        }
        const float s128 = fmaf((float)d, DPf, OFFf);
        const float ax0 = fmaf(-s128, sv, 127.5f);
        const float ay0 = fmaf( s128, cv, 127.5f);
        const bool steep = fabsf(sv) > fabsf(cv);
        const float c2 = steep ? sv : cv;
        const float s2 = steep ? cv : sv;
        const float ax = steep ? ay0 : ax0;
        const float ay = steep ? ax0 : ay0;

        float lo = -1e30f, hi = 1e30f, li = -1e30f, hii = 1e30f;
        bool empty = false, iempty = false;
        slab(ax, c2, -1.001f, 256.001f, lo, hi, empty);
        slab(ay, s2, -1.001f, 256.001f, lo, hi, empty);
        slab(ax, c2, 0.001f, 254.999f, li, hii, iempty);
        slab(ay, s2, 0.001f, 254.999f, li, hii, iempty);

        int kLo = 1, kHi = 0, kiLo = 1, kiHi = 0;
        if (!empty && lo <= hi) {
            kLo = max(0,     (int)ceilf ((lo - OFFf) * INV_DPf - 0.001f));
            kHi = min(S - 1, (int)floorf((hi - OFFf) * INV_DPf + 0.001f));
            if (kLo > kHi) { kLo = 1; kHi = 0; kiLo = 1; kiHi = 0; }
            else if (iempty || li > hii) { kiLo = kHi + 1; kiHi = kHi; }
            else {
                kiLo = max(kLo, (int)ceilf ((li  - OFFf) * INV_DPf + 0.001f));
                kiHi = min(kHi, (int)floorf((hii - OFFf) * INV_DPf - 0.001f));
                if (kiLo > kiHi) { kiLo = kHi + 1; kiHi = kHi; }
            }
        }
        g_bounds[v * D + d] = make_ushort4((unsigned short)kLo, (unsigned short)kiLo,
                                           (unsigned short)kiHi, (unsigned short)kHi);
    }

    __syncthreads();
    {
        int xo = bx + ty, yo = by + tx;
        g_img2T[xo * H + yo] = tile[tx][ty];
    }
}

__device__ __forceinline__ void accum4(float2 p00, float2 p10, float2 p01, float2 p11,
                                       float fx, float fy, float& sA, float& sB) {
    float gx = 1.f - fx, gy = 1.f - fy;
    float w00 = gx * gy, w10 = fx * gy, w01 = gx * fy, w11 = fx * fy;
    sA = fmaf(p00.x, w00, fmaf(p10.x, w10, fmaf(p01.x, w01, fmaf(p11.x, w11, sA))));
    sB = fmaf(p00.y, w00, fmaf(p10.y, w10, fmaf(p01.y, w01, fmaf(p11.y, w11, sB))));
}

// ---------------------------------------------------------------------------
// forward projection: one warp per (v,d) ray, lanes stride over samples.
// Steep angles read the transposed image (bitwise-identical bilinear).
// ---------------------------------------------------------------------------
__global__ void __launch_bounds__(256) fwd_kernel(const float* __restrict__ proj) {
    const int warp = (blockIdx.x * blockDim.x + threadIdx.x) >> 5;
    const int lane = threadIdx.x & 31;
    const int v = warp >> 8;
    const int d = warp & 255;

    const float2 tv = g_trigB[v];
    const float cv = tv.x, sv = tv.y;
    const ushort4 bn = g_bounds[warp];
    const int kLo = bn.x, kiLo = bn.y, kiHi = bn.z, kHi = bn.w;

    const float s128 = fmaf((float)d, DPf, OFFf);
    const float ax0 = fmaf(-s128, sv, 127.5f);
    const float ay0 = fmaf( s128, cv, 127.5f);
    const bool steep = fabsf(sv) > fabsf(cv);
    const float2* __restrict__ im = steep ? g_img2T : g_img2;
    const float c2 = steep ? sv : cv;
    const float s2 = steep ? cv : sv;
    const float ax = steep ? ay0 : ax0;
    const float ay = steep ? ax0 : ay0;

    float sA = 0.f, sB = 0.f;

    for (int k = kLo + lane; k < kiLo; k += 32) {
        float t128 = fmaf((float)k, DPf, OFFf);
        float xp = fmaf(t128, c2, ax), yp = fmaf(t128, s2, ay);
        float x0f = floorf(xp), y0f = floorf(yp);
        int ix0 = (int)x0f, iy0 = (int)y0f;
        int base = iy0 * W + ix0;
        float2 z = make_float2(0.f, 0.f);
        float2 p00 = z, p10 = z, p01 = z, p11 = z;
        bool vx0 = (unsigned)ix0       < (unsigned)W;
        bool vx1 = (unsigned)(ix0 + 1) < (unsigned)W;
        bool vy0 = (unsigned)iy0       < (unsigned)H;
        bool vy1 = (unsigned)(iy0 + 1) < (unsigned)H;
        if (vx0 && vy0) p00 = im[base];
        if (vx1 && vy0) p10 = im[base + 1];
        if (vx0 && vy1) p01 = im[base + W];
        if (vx1 && vy1) p11 = im[base + W + 1];
        accum4(p00, p10, p01, p11, xp - x0f, yp - y0f, sA, sB);
    }
    for (int k = kiLo + lane; k <= kiHi; k += 32) {
        float t128 = fmaf((float)k, DPf, OFFf);
        float xp = fmaf(t128, c2, ax), yp = fmaf(t128, s2, ay);
        float x0f = floorf(xp), y0f = floorf(yp);
        int base = (int)y0f * W + (int)x0f;
        float2 p00 = im[base],     p10 = im[base + 1];
        float2 p01 = im[base + W], p11 = im[base + W + 1];
        accum4(p00, p10, p01, p11, xp - x0f, yp - y0f, sA, sB);
    }
    for (int k = max(kiHi + 1, kLo) + lane; k <= kHi; k += 32) {
        float t128 = fmaf((float)k, DPf, OFFf);
        float xp = fmaf(t128, c2, ax), yp = fmaf(t128, s2, ay);
        float x0f = floorf(xp), y0f = floorf(yp);
        int ix0 = (int)x0f, iy0 = (int)y0f;
        int base = iy0 * W + ix0;
        float2 z = make_float2(0.f, 0.f);
        float2 p00 = z, p10 = z, p01 = z, p11 = z;
        bool vx0 = (unsigned)ix0       < (unsigned)W;
        bool vx1 = (unsigned)(ix0 + 1) < (unsigned)W;
        bool vy0 = (unsigned)iy0       < (unsigned)H;
        bool vy1 = (unsigned)(iy0 + 1) < (unsigned)H;
        if (vx0 && vy0) p00 = im[base];
        if (vx1 && vy0) p10 = im[base + 1];
        if (vx0 && vy1) p01 = im[base + W];
        if (vx1 && vy1) p11 = im[base + W + 1];
        accum4(p00, p10, p01, p11, xp - x0f, yp - y0f, sA, sB);
    }

    #pragma unroll
    for (int o = 16; o; o >>= 1) {
        sA += __shfl_xor_sync(0xffffffffu, sA, o);
        sB += __shfl_xor_sync(0xffffffffu, sB, o);
    }
    if (lane == 0) {
        g_temp[warp] = make_float2(fmaf(DTf, sA, -__ldg(proj + warp)),
                                   fmaf(DTf, sB, -__ldg(proj + V * D + warp)));
    }
}

// ---------------------------------------------------------------------------
// backprojection + update, 90-degree angle pairing:
// sample (v+96, 255-k, j) is at the same image point as sample (v, j, k),
// so one geometry evaluation (8 hats -> 4 products) serves BOTH angles:
//   v    : q0 = P00+P01 (det j0),      q1 = P10+P11 (det j0+1)
//   v+96 : r0 = P01+P11 (det 254-k0),  r1 = P00+P10 (det 255-k0)
// One pixel per thread (full occupancy), loop over 96 angle pairs.
// ---------------------------------------------------------------------------
__global__ void __launch_bounds__(128) bwd_kernel(const float* __restrict__ wptr,
                                                  float* __restrict__ out) {
    __shared__ float4 sg[V / 2];
    const int tid = threadIdx.x;
    #pragma unroll
    for (int i = tid; i < V / 2; i += 128) sg[i] = g_trig4[i];
    __syncthreads();

    const int p = blockIdx.x * 128 + tid;
    const int ix = p & (W - 1);
    const int iy = p >> 8;
    const float px = (float)ix - 127.5f;
    const float py = (float)iy - 127.5f;
    const float npx = -px;

    float accA = 0.f, accB = 0.f;
    const float2* __restrict__ row  = g_temp;             // angle v
    const float2* __restrict__ rowm = g_temp + 96 * D;    // angle v+96

    #pragma unroll 2
    for (int v = 0; v < V / 2; ++v, row += D, rowm += D) {
        const float4 q = sg[v];
        const float svDP = q.x, cvDP = q.y, svI = q.z, cvI = q.w;

        const float jc = fmaf(py, cvI, fmaf(npx, svI, 127.5f));
        const float kc = fmaf(px, cvI, fmaf(py,  svI, 127.5f));
        const float jf = floorf(jc), kf = floorf(kc);
        const float fj = jc - jf,    fk = kc - kf;
        const int   j0 = (int)jf;
        const int   k0 = (int)kf;

        const float dx00 = fmaf(fj, svDP, -(fk * cvDP));
        const float u    = fmaf(fj, cvDP,  (fk * svDP));
        const float dx10 = dx00 - svDP;
        const float dx01 = dx00 + cvDP;
        const float dx11 = dx10 + cvDP;
        const float e10  = u - cvDP;
        const float e01  = u - svDP;
        const float e11  = e10 - svDP;

        const float hx00 = __saturatef(1.f - fabsf(dx00));
        const float hx10 = __saturatef(1.f - fabsf(dx10));
        const float hx01 = __saturatef(1.f - fabsf(dx01));
        const float hx11 = __saturatef(1.f - fabsf(dx11));
        const float hy00 = __saturatef(1.f - fabsf(u));
        const float hy10 = __saturatef(1.f - fabsf(e10));
        const float hy01 = __saturatef(1.f - fabsf(e01));
        const float hy11 = __saturatef(1.f - fabsf(e11));

        const float P00 = hx00 * hy00;
        const float P10 = hx10 * hy10;
        const float P01 = hx01 * hy01;
        const float P11 = hx11 * hy11;

        const float q0 = P00 + P01, q1 = P10 + P11;   // angle v
        const float r0 = P01 + P11, r1 = P00 + P10;   // angle v+96

        const float2 t0 = __ldg(row + j0);
        const float2 t1 = __ldg(row + j0 + 1);
        const float2 m0 = __ldg(rowm + (254 - k0));
        const float2 m1 = __ldg(rowm + (255 - k0));
        accA = fmaf(t0.x, q0, fmaf(t1.x, q1, fmaf(m0.x, r0, fmaf(m1.x, r1, accA))));
        accB = fmaf(t0.y, q0, fmaf(t1.y, q1, fmaf(m0.y, r0, fmaf(m1.y, r1, accB))));
    }

    const float wdt = __ldg(wptr) * DTf;
    const float2 ia = g_img2[p];
    out[p]      = fmaf(-wdt, accA, ia.x);
    out[p + HW] = fmaf(-wdt, accB, ia.y);
}

// ---------------------------------------------------------------------------
extern "C" void kernel_launch(void* const* d_in, const int* in_sizes, int n_in,
                              void* d_out, int out_size) {
    const float* img  = (const float*)d_in[0];   // [2,1,256,256]
    const float* proj = (const float*)d_in[1];   // [2,1,192,256]
    const float* wptr = (const float*)d_in[2];   // [1]
    float* out = (float*)d_out;                  // [2,1,256,256]

    prep_kernel<<<256, 256>>>(img);
    fwd_kernel<<<(V * D * 32) / 256, 256>>>(proj);
    bwd_kernel<<<HW / 128, 128>>>(wptr, out);
}